// round 3
// baseline (speedup 1.0000x reference)
#include <cuda_runtime.h>
#include <math.h>

#define W_DIM 512
#define F_DIM 512
#define FIN   1024
#define NH    8
#define DH    64
#define NLAYER 12
#define EPSV  1e-5f

// ---------------- scratch (device globals; no allocations allowed) ----------
__device__ float g_e  [4 * 512 * 512];
__device__ float g_h  [4 * 512 * 512];
__device__ float g_q  [4 * 512 * 512];
__device__ float g_k  [4 * 512 * 512];
__device__ float g_v  [4 * 512 * 512];
__device__ float g_tmp[4 * 512 * 512];
__device__ float g_big[4 * 2048 * 512];
__device__ float g_s  [32 * 512 * 512];

// ---------------- batched GEMM: C[bc] = Wt[c] @ X[bc] (+res, +sqrelu) -------
// Wt: (M,K) row-major per channel c = bc&1 ; X: (K,N) row-major per bc ; N=512
template<bool SQRELU, bool HASRES>
__global__ void __launch_bounds__(256) gemm_nn(
    const float* __restrict__ A, const float* __restrict__ B,
    const float* __restrict__ Res, float* __restrict__ Cout,
    int M, int N, int K)
{
    int bc = blockIdx.z;
    const float* Ab = A + (size_t)(bc & 1) * M * K;
    const float* Bb = B + (size_t)bc * K * N;
    float* Cb = Cout + (size_t)bc * M * N;
    const float* Rb = HASRES ? (Res + (size_t)bc * M * N) : nullptr;

    __shared__ float As[64][17];
    __shared__ float Bs[16][64];

    int tid = threadIdx.x;
    int tx = tid & 15, ty = tid >> 4;
    int m0 = blockIdx.y * 64, n0 = blockIdx.x * 64;

    float acc[4][4] = {};

    for (int k0 = 0; k0 < K; k0 += 16) {
        #pragma unroll
        for (int i = 0; i < 4; i++) {
            int idx = tid + i * 256;
            int mr = idx >> 4, kc = idx & 15;
            As[mr][kc] = Ab[(size_t)(m0 + mr) * K + k0 + kc];
        }
        #pragma unroll
        for (int i = 0; i < 4; i++) {
            int idx = tid + i * 256;
            int kr = idx >> 6, nc = idx & 63;
            Bs[kr][nc] = Bb[(size_t)(k0 + kr) * N + n0 + nc];
        }
        __syncthreads();
        #pragma unroll
        for (int kk = 0; kk < 16; kk++) {
            float a0 = As[ty * 4 + 0][kk];
            float a1 = As[ty * 4 + 1][kk];
            float a2 = As[ty * 4 + 2][kk];
            float a3 = As[ty * 4 + 3][kk];
            float4 b = *reinterpret_cast<const float4*>(&Bs[kk][tx * 4]);
            acc[0][0] += a0 * b.x; acc[0][1] += a0 * b.y; acc[0][2] += a0 * b.z; acc[0][3] += a0 * b.w;
            acc[1][0] += a1 * b.x; acc[1][1] += a1 * b.y; acc[1][2] += a1 * b.z; acc[1][3] += a1 * b.w;
            acc[2][0] += a2 * b.x; acc[2][1] += a2 * b.y; acc[2][2] += a2 * b.z; acc[2][3] += a2 * b.w;
            acc[3][0] += a3 * b.x; acc[3][1] += a3 * b.y; acc[3][2] += a3 * b.z; acc[3][3] += a3 * b.w;
        }
        __syncthreads();
    }

    #pragma unroll
    for (int i = 0; i < 4; i++) {
        int m = m0 + ty * 4 + i;
        #pragma unroll
        for (int j = 0; j < 4; j++) {
            int n = n0 + tx * 4 + j;
            float v = acc[i][j];
            if (SQRELU) { float r = fmaxf(v, 0.f); v = r * r; }
            if (HASRES) v += Rb[(size_t)m * N + n];
            Cb[(size_t)m * N + n] = v;
        }
    }
}

// ---------------- channel mix: Y[b,d,f,w] = dw[d,0]X[b,0,f,w]+dw[d,1]X[b,1,f,w]
template<bool SQRELU, bool HASADD>
__global__ void __launch_bounds__(256) mix_k(
    const float* __restrict__ X, const float* __restrict__ dw,
    const float* __restrict__ Add, float* __restrict__ Y, int Fd)
{
    int idx = blockIdx.x * 256 + threadIdx.x;
    int total = 4 * Fd * W_DIM;
    if (idx >= total) return;
    int w = idx & 511;
    int f = (idx >> 9) % Fd;
    int bd = idx / (512 * Fd);
    int b = bd >> 1, d = bd & 1;
    size_t base = ((size_t)(b * 2) * Fd + f) * W_DIM + w;
    float v = dw[d * 2 + 0] * X[base] + dw[d * 2 + 1] * X[base + (size_t)Fd * W_DIM];
    if (SQRELU) { float r = fmaxf(v, 0.f); v = r * r; }
    if (HASADD) v += Add[idx];
    Y[idx] = v;
}

// ---------------- channel mix + RoPE (F=512) --------------------------------
__global__ void __launch_bounds__(256) mix_rope_k(
    const float* __restrict__ X, const float* __restrict__ dw,
    float* __restrict__ Y)
{
    int idx = blockIdx.x * 256 + threadIdx.x;  // 4 * 256 * 512 = 524288 pairs
    int w  = idx & 511;
    int fp = (idx >> 9) & 255;
    int bd = idx >> 17;
    int b = bd >> 1, d = bd & 1;
    int f0 = fp * 2;
    size_t b0 = ((size_t)(b * 2) * F_DIM + f0) * W_DIM + w;
    float d0 = dw[d * 2 + 0], d1 = dw[d * 2 + 1];
    float v0 = d0 * X[b0]          + d1 * X[b0 + (size_t)F_DIM * W_DIM];
    float v1 = d0 * X[b0 + W_DIM]  + d1 * X[b0 + W_DIM + (size_t)F_DIM * W_DIM];
    int i = fp & 31;                       // pair index within head (dh=64)
    float inv = powf(10000.f, -(float)(2 * i) / 64.f);
    float ang = (float)w * inv;
    float sn, cs;
    sincosf(ang, &sn, &cs);
    size_t o0 = ((size_t)bd * F_DIM + f0) * W_DIM + w;
    Y[o0]          = v0 * cs - v1 * sn;
    Y[o0 + W_DIM]  = v1 * cs + v0 * sn;
}

// ---------------- frame_norm: LN over F per (b,c,w) --------------------------
__global__ void frame_norm_k(
    const float* __restrict__ X, const float* __restrict__ gw,
    const float* __restrict__ gb, float* __restrict__ Y)
{
    int bc = blockIdx.y;
    int c = bc & 1;
    int tx = threadIdx.x, ty = threadIdx.y;
    int w = blockIdx.x * 32 + tx;
    const float* Xb = X + (size_t)bc * F_DIM * W_DIM;
    float* Yb = Y + (size_t)bc * F_DIM * W_DIM;

    float sum = 0.f, sq = 0.f;
    for (int f = ty; f < F_DIM; f += 8) {
        float v = Xb[(size_t)f * W_DIM + w];
        sum += v; sq += v * v;
    }
    __shared__ float ss[8][33], s2[8][33];
    __shared__ float smu[32], srs[32];
    ss[ty][tx] = sum; s2[ty][tx] = sq;
    __syncthreads();
    if (ty == 0) {
        for (int r = 1; r < 8; r++) { sum += ss[r][tx]; sq += s2[r][tx]; }
        float mu = sum * (1.f / 512.f);
        float var = sq * (1.f / 512.f) - mu * mu;
        smu[tx] = mu;
        srs[tx] = rsqrtf(var + EPSV);
    }
    __syncthreads();
    float mu = smu[tx], rs = srs[tx];
    for (int f = ty; f < F_DIM; f += 8) {
        float v = Xb[(size_t)f * W_DIM + w];
        Yb[(size_t)f * W_DIM + w] = (v - mu) * rs * gw[c * F_DIM + f] + gb[c * F_DIM + f];
    }
}

// ---------------- attention scores: S[q,k] = scale * sum_d Q[d,q]K[d,k] ------
__global__ void __launch_bounds__(256) attn_scores_k(
    const float* __restrict__ Q, const float* __restrict__ Kt,
    float* __restrict__ S)
{
    int batch = blockIdx.z;                    // 32 = bc*8 + h
    int bc = batch >> 3, h = batch & 7;
    const float* Qb = Q + ((size_t)bc * F_DIM + h * DH) * W_DIM;
    const float* Kb = Kt + ((size_t)bc * F_DIM + h * DH) * W_DIM;
    float* Sb = S + (size_t)batch * W_DIM * W_DIM;

    __shared__ float Qs[16][64];
    __shared__ float Ks[16][64];
    int tid = threadIdx.x;
    int tx = tid & 15, ty = tid >> 4;
    int q0 = blockIdx.y * 64, k0 = blockIdx.x * 64;
    float acc[4][4] = {};

    for (int d0 = 0; d0 < DH; d0 += 16) {
        #pragma unroll
        for (int i = 0; i < 4; i++) {
            int idx = tid + i * 256;
            int r = idx >> 6, cc = idx & 63;
            Qs[r][cc] = Qb[(size_t)(d0 + r) * W_DIM + q0 + cc];
            Ks[r][cc] = Kb[(size_t)(d0 + r) * W_DIM + k0 + cc];
        }
        __syncthreads();
        #pragma unroll
        for (int kk = 0; kk < 16; kk++) {
            float4 qa = *reinterpret_cast<const float4*>(&Qs[kk][ty * 4]);
            float4 kb = *reinterpret_cast<const float4*>(&Ks[kk][tx * 4]);
            float qv[4] = {qa.x, qa.y, qa.z, qa.w};
            float kv[4] = {kb.x, kb.y, kb.z, kb.w};
            #pragma unroll
            for (int i = 0; i < 4; i++)
                #pragma unroll
                for (int j = 0; j < 4; j++)
                    acc[i][j] += qv[i] * kv[j];
        }
        __syncthreads();
    }
    const float scale = 0.044194173824159216f;  // 1/sqrt(512)
    #pragma unroll
    for (int i = 0; i < 4; i++)
        #pragma unroll
        for (int j = 0; j < 4; j++)
            Sb[(size_t)(q0 + ty * 4 + i) * W_DIM + (k0 + tx * 4 + j)] = acc[i][j] * scale;
}

// ---------------- softmax over rows of S (warp per row) ----------------------
__global__ void __launch_bounds__(256) softmax_rows_k(float* __restrict__ S)
{
    int row = blockIdx.x * 8 + (threadIdx.x >> 5);
    int lane = threadIdx.x & 31;
    float* p = S + (size_t)row * W_DIM;
    float v[16];
    float mx = -1e30f;
    #pragma unroll
    for (int i = 0; i < 16; i++) { v[i] = p[lane + i * 32]; mx = fmaxf(mx, v[i]); }
    #pragma unroll
    for (int o = 16; o; o >>= 1) mx = fmaxf(mx, __shfl_xor_sync(0xffffffffu, mx, o));
    float sum = 0.f;
    #pragma unroll
    for (int i = 0; i < 16; i++) { v[i] = __expf(v[i] - mx); sum += v[i]; }
    #pragma unroll
    for (int o = 16; o; o >>= 1) sum += __shfl_xor_sync(0xffffffffu, sum, o);
    float inv = 1.f / sum;
    #pragma unroll
    for (int i = 0; i < 16; i++) p[lane + i * 32] = v[i] * inv;
}

// ---------------- attention output: O[d,q] = sum_k V[d,k] P[q,k] -------------
__global__ void __launch_bounds__(256) attn_out_k(
    const float* __restrict__ P, const float* __restrict__ V,
    float* __restrict__ O)
{
    int batch = blockIdx.z;
    int bc = batch >> 3, h = batch & 7;
    const float* Vb = V + ((size_t)bc * F_DIM + h * DH) * W_DIM;
    const float* Pb = P + (size_t)batch * W_DIM * W_DIM;
    float* Ob = O + ((size_t)bc * F_DIM + h * DH) * W_DIM;

    __shared__ float Vs[16][65];
    __shared__ float Ps[16][65];
    int tid = threadIdx.x;
    int tx = tid & 15, ty = tid >> 4;
    int q0 = blockIdx.x * 64;
    float acc[4][4] = {};

    for (int k0 = 0; k0 < W_DIM; k0 += 16) {
        #pragma unroll
        for (int i = 0; i < 4; i++) {
            int idx = tid + i * 256;
            int dd = idx >> 4, kc = idx & 15;
            Vs[kc][dd] = Vb[(size_t)dd * W_DIM + k0 + kc];
            Ps[kc][dd] = Pb[(size_t)(q0 + dd) * W_DIM + k0 + kc];
        }
        __syncthreads();
        #pragma unroll
        for (int kk = 0; kk < 16; kk++) {
            float av[4], bv[4];
            #pragma unroll
            for (int i = 0; i < 4; i++) av[i] = Vs[kk][ty * 4 + i];
            #pragma unroll
            for (int j = 0; j < 4; j++) bv[j] = Ps[kk][tx * 4 + j];
            #pragma unroll
            for (int i = 0; i < 4; i++)
                #pragma unroll
                for (int j = 0; j < 4; j++)
                    acc[i][j] += av[i] * bv[j];
        }
        __syncthreads();
    }
    #pragma unroll
    for (int i = 0; i < 4; i++)
        #pragma unroll
        for (int j = 0; j < 4; j++)
            Ob[(size_t)(ty * 4 + i) * W_DIM + q0 + tx * 4 + j] = acc[i][j];
}

// ---------------- host orchestration ----------------------------------------
extern "C" void kernel_launch(void* const* d_in, const int* in_sizes, int n_in,
                              void* d_out, int out_size)
{
    const float* x     = (const float*)d_in[0];
    const float* e1_pw = (const float*)d_in[1];
    const float* e1_dw = (const float*)d_in[2];
    const float* e2_pw = (const float*)d_in[3];
    const float* e2_dw = (const float*)d_in[4];
    const float* ei_pw = (const float*)d_in[5];
    const float* ei_dw = (const float*)d_in[6];
    const float* n1_w  = (const float*)d_in[7];
    const float* n1_b  = (const float*)d_in[8];
    const float* q_pw  = (const float*)d_in[9];
    const float* q_dw  = (const float*)d_in[10];
    const float* k_pw  = (const float*)d_in[11];
    const float* k_dw  = (const float*)d_in[12];
    const float* v_pw  = (const float*)d_in[13];
    const float* v_dw  = (const float*)d_in[14];
    const float* o_pw  = (const float*)d_in[15];
    const float* n2_w  = (const float*)d_in[16];
    const float* n2_b  = (const float*)d_in[17];
    const float* f1_pw = (const float*)d_in[18];
    const float* f2_pw = (const float*)d_in[19];
    const float* d1_pw = (const float*)d_in[20];
    const float* d1_dw = (const float*)d_in[21];
    const float* d2_pw = (const float*)d_in[22];
    const float* d2_dw = (const float*)d_in[23];
    const float* di_pw = (const float*)d_in[24];
    const float* di_dw = (const float*)d_in[25];
    float* out = (float*)d_out;

    float *e, *h, *q, *k, *v, *tmp, *big, *s;
    cudaGetSymbolAddress((void**)&e,   g_e);
    cudaGetSymbolAddress((void**)&h,   g_h);
    cudaGetSymbolAddress((void**)&q,   g_q);
    cudaGetSymbolAddress((void**)&k,   g_k);
    cudaGetSymbolAddress((void**)&v,   g_v);
    cudaGetSymbolAddress((void**)&tmp, g_tmp);
    cudaGetSymbolAddress((void**)&big, g_big);
    cudaGetSymbolAddress((void**)&s,   g_s);

    dim3 g512(8, 8, 4);           // M=512 GEMM
    dim3 gf1 (8, 32, 4);          // M=2048
    dim3 g1024(8, 16, 4);         // M=1024
    dim3 lnG(16, 4), lnB(32, 8);
    int mixG512  = (4 * 512 * 512) / 256;   // 4096
    int mixG1024 = (4 * 1024 * 512) / 256;  // 8192
    int ropeG    = (4 * 256 * 512) / 256;   // 2048

    // ---------------- encoder frame_block ----------------
    gemm_nn<false, false><<<g512, 256>>>(e1_pw, x, nullptr, tmp, 512, 512, 1024);
    mix_k<true, false><<<mixG512, 256>>>(tmp, e1_dw, nullptr, h, 512);
    gemm_nn<false, false><<<g512, 256>>>(e2_pw, h, nullptr, tmp, 512, 512, 512);
    mix_k<false, false><<<mixG512, 256>>>(tmp, e2_dw, nullptr, q, 512);   // z -> q
    gemm_nn<false, false><<<g512, 256>>>(ei_pw, x, nullptr, tmp, 512, 512, 1024);
    mix_k<false, true><<<mixG512, 256>>>(tmp, ei_dw, q, e, 512);          // e = id + z

    // ---------------- layers ----------------
    for (int i = 0; i < NLAYER; i++) {
        const float* qpw = q_pw + (size_t)i * 2 * 512 * 512;
        const float* kpw = k_pw + (size_t)i * 2 * 512 * 512;
        const float* vpw = v_pw + (size_t)i * 2 * 512 * 512;
        const float* opw = o_pw + (size_t)i * 2 * 512 * 512;
        const float* f1w = f1_pw + (size_t)i * 2 * 2048 * 512;
        const float* f2w = f2_pw + (size_t)i * 2 * 512 * 2048;

        frame_norm_k<<<lnG, lnB>>>(e, n1_w + (size_t)i * 1024, n1_b + (size_t)i * 1024, h);

        gemm_nn<false, false><<<g512, 256>>>(qpw, h, nullptr, tmp, 512, 512, 512);
        mix_rope_k<<<ropeG, 256>>>(tmp, q_dw + i * 4, q);
        gemm_nn<false, false><<<g512, 256>>>(kpw, h, nullptr, tmp, 512, 512, 512);
        mix_rope_k<<<ropeG, 256>>>(tmp, k_dw + i * 4, k);
        gemm_nn<false, false><<<g512, 256>>>(vpw, h, nullptr, tmp, 512, 512, 512);
        mix_k<false, false><<<mixG512, 256>>>(tmp, v_dw + i * 4, nullptr, v, 512);

        attn_scores_k<<<dim3(8, 8, 32), 256>>>(q, k, s);
        softmax_rows_k<<<2048, 256>>>(s);
        attn_out_k<<<dim3(8, 1, 32), 256>>>(s, v, h);

        gemm_nn<false, true><<<g512, 256>>>(opw, h, e, e, 512, 512, 512);   // e += O

        frame_norm_k<<<lnG, lnB>>>(e, n2_w + (size_t)i * 1024, n2_b + (size_t)i * 1024, h);
        gemm_nn<true, false><<<gf1, 256>>>(f1w, h, nullptr, big, 2048, 512, 512);
        gemm_nn<false, true><<<g512, 256>>>(f2w, big, e, e, 512, 512, 2048); // e += FFN
    }

    // ---------------- decoder frame_block ----------------
    float* ta = big;                 // (4,1024,512) scratch
    float* tb = s;                   // (4,1024,512) scratch
    float* tz = s + 2097152;         // (4,1024,512) scratch
    gemm_nn<false, false><<<g1024, 256>>>(d1_pw, e, nullptr, ta, 1024, 512, 512);
    mix_k<true, false><<<mixG1024, 256>>>(ta, d1_dw, nullptr, tb, 1024);
    gemm_nn<false, false><<<g1024, 256>>>(d2_pw, tb, nullptr, ta, 1024, 512, 1024);
    mix_k<false, false><<<mixG1024, 256>>>(ta, d2_dw, nullptr, tz, 1024);
    gemm_nn<false, false><<<g1024, 256>>>(di_pw, e, nullptr, ta, 1024, 512, 512);
    mix_k<false, true><<<mixG1024, 256>>>(ta, di_dw, tz, out, 1024);
}

// round 6
// speedup vs baseline: 1.2708x; 1.2708x over previous
#include <cuda_runtime.h>
#include <cuda_bf16.h>
#include <math.h>
#include <stdint.h>

#define NLAYER 12
#define EPSV 1e-5f

__device__ float g_e  [1048576];
__device__ float g_h  [1048576];
__device__ float g_q  [1048576];
__device__ float g_k  [1048576];
__device__ float g_v  [1048576];
__device__ float g_big[4194304];
__device__ float g_s  [8388608];

__device__ __forceinline__ uint32_t smem_u32(const void* p) {
    uint32_t a;
    asm("{ .reg .u64 t; cvta.to.shared.u64 t, %1; cvt.u32.u64 %0, t; }" : "=r"(a) : "l"(p));
    return a;
}
#define SWZ(x) ((x) ^ (((x) >> 3) & 0x70))

__device__ __forceinline__ void ldsm4(uint32_t* r, uint32_t a) {
    asm volatile("ldmatrix.sync.aligned.m8n8.x4.shared.b16 {%0,%1,%2,%3}, [%4];"
                 : "=r"(r[0]), "=r"(r[1]), "=r"(r[2]), "=r"(r[3]) : "r"(a));
}
__device__ __forceinline__ void mma16816(float* c, const uint32_t* a, const uint32_t* b) {
    asm volatile(
        "mma.sync.aligned.m16n8k16.row.col.f32.bf16.bf16.f32 "
        "{%0,%1,%2,%3}, {%4,%5,%6,%7}, {%8,%9}, {%0,%1,%2,%3};"
        : "+f"(c[0]), "+f"(c[1]), "+f"(c[2]), "+f"(c[3])
        : "r"(a[0]), "r"(a[1]), "r"(a[2]), "r"(a[3]), "r"(b[0]), "r"(b[1]));
}
__device__ __forceinline__ void splt(float v, unsigned short& h, unsigned short& l) {
    __nv_bfloat16 hb = __float2bfloat16(v);
    h = __bfloat16_as_ushort(hb);
    l = __bfloat16_as_ushort(__float2bfloat16(v - __bfloat162float(hb)));
}

// natural K-major split: src (nrows x 64 f32), row stride ld -> swizzled bf16 tiles
__device__ __forceinline__ void nload(char* dH, char* dL, const float* src, int ld, int nrows, int tid) {
    for (int it = tid; it < nrows * 16; it += 256) {
        int r = it >> 4, cg = it & 15;
        float4 x = *reinterpret_cast<const float4*>(src + (size_t)r * ld + cg * 4);
        unsigned short hh[4], ll[4];
        splt(x.x, hh[0], ll[0]); splt(x.y, hh[1], ll[1]);
        splt(x.z, hh[2], ll[2]); splt(x.w, hh[3], ll[3]);
        uint32_t off = SWZ((uint32_t)(r * 128 + cg * 8));
        *reinterpret_cast<uint2*>(dH + off) = *reinterpret_cast<uint2*>(hh);
        *reinterpret_cast<uint2*>(dL + off) = *reinterpret_cast<uint2*>(ll);
    }
}
// transpose split: src (64 k-rows x NR n-cols, stride ld) -> tile (NR rows x 64 k)
template<int NR>
__device__ __forceinline__ void tloadT(char* dH, char* dL, const float* src, int ld, int tid) {
    const int SH = (NR == 128) ? 7 : 6;
    for (int it = tid; it < NR * 32; it += 256) {
        int n = it & (NR - 1), kp = it >> SH;
        float a = src[(size_t)(2 * kp) * ld + n];
        float b = src[(size_t)(2 * kp + 1) * ld + n];
        unsigned short h0, l0, h1, l1;
        splt(a, h0, l0); splt(b, h1, l1);
        uint32_t off = SWZ((uint32_t)(n * 128 + kp * 4));
        *reinterpret_cast<uint32_t*>(dH + off) = (uint32_t)h0 | ((uint32_t)h1 << 16);
        *reinterpret_cast<uint32_t*>(dL + off) = (uint32_t)l0 | ((uint32_t)l1 << 16);
    }
}

// warp computes 32m x (NT*8)n over one K-chunk of 64 with 3-term split
template<int NT>
__device__ __forceinline__ void mma_chunk(
    float (&acc)[2][NT][4], uint32_t aHi, uint32_t aLo, uint32_t bHi, uint32_t bLo,
    int wm, int wn, int lane)
{
    int la = lane & 7, j = lane >> 3;
    #pragma unroll
    for (int ks = 0; ks < 4; ks++) {
        uint32_t ah[2][4], al[2][4];
        #pragma unroll
        for (int mi = 0; mi < 2; mi++) {
            uint32_t off = SWZ((uint32_t)((wm * 32 + mi * 16 + ((j & 1) << 3) + la) * 128 + ks * 32 + ((j >> 1) << 4)));
            ldsm4(ah[mi], aHi + off);
            ldsm4(al[mi], aLo + off);
        }
        uint32_t bh[NT][2], bl[NT][2];
        #pragma unroll
        for (int nt = 0; nt < NT; nt += 2) {
            uint32_t off = SWZ((uint32_t)((wn * NT * 8 + nt * 8 + ((j >> 1) << 3) + la) * 128 + ks * 32 + ((j & 1) << 4)));
            uint32_t t[4];
            ldsm4(t, bHi + off);
            bh[nt][0] = t[0]; bh[nt][1] = t[1]; bh[nt + 1][0] = t[2]; bh[nt + 1][1] = t[3];
            ldsm4(t, bLo + off);
            bl[nt][0] = t[0]; bl[nt][1] = t[1]; bl[nt + 1][0] = t[2]; bl[nt + 1][1] = t[3];
        }
        #pragma unroll
        for (int mi = 0; mi < 2; mi++)
            #pragma unroll
            for (int nt = 0; nt < NT; nt++) {
                mma16816(acc[mi][nt], ah[mi], bh[nt]);
                mma16816(acc[mi][nt], ah[mi], bl[nt]);
                mma16816(acc[mi][nt], al[mi], bh[nt]);
            }
    }
}

// ---------------- dense GEMM: C[proj][bc] = W[proj][c] @ X[bc], N=512 --------
template<int EPI>  // 0 none, 1 sqrelu, 2 +res
__global__ void __launch_bounds__(256) gemm_mma(
    const float* __restrict__ W0, const float* __restrict__ W1, const float* __restrict__ W2,
    const float* __restrict__ X, const float* __restrict__ Res, float* __restrict__ C,
    int M, int K)
{
    __shared__ char sm[49152];
    uint32_t sb = smem_u32(sm);
    int tid = threadIdx.x, wid = tid >> 5, lane = tid & 31;
    int wm = wid >> 2, wn = wid & 3;
    int proj = blockIdx.z >> 2, bc = blockIdx.z & 3, c = bc & 1;
    const float* Wp = proj == 0 ? W0 : (proj == 1 ? W1 : W2);
    const float* A = Wp + (size_t)c * M * K;
    const float* B = X + (size_t)bc * K * 512;
    float* Cb = C + (size_t)(proj * 4 + bc) * M * 512;
    int m0 = blockIdx.y * 64, n0 = blockIdx.x * 128;

    float acc[2][4][4] = {};
    int NC = K >> 6;
    for (int ch = 0; ch < NC; ch++) {
        __syncthreads();
        nload(sm, sm + 8192, A + (size_t)m0 * K + ch * 64, K, 64, tid);
        tloadT<128>(sm + 16384, sm + 32768, B + (size_t)(ch * 64) * 512 + n0, 512, tid);
        __syncthreads();
        mma_chunk<4>(acc, sb, sb + 8192, sb + 16384, sb + 32768, wm, wn, lane);
    }
    __syncthreads();
    float* stg = (float*)sm;
    #pragma unroll
    for (int mi = 0; mi < 2; mi++)
        #pragma unroll
        for (int nt = 0; nt < 4; nt++) {
            int row = wm * 32 + mi * 16 + (lane >> 2);
            int col = wn * 32 + nt * 8 + (lane & 3) * 2;
            stg[row * 132 + col] = acc[mi][nt][0];
            stg[row * 132 + col + 1] = acc[mi][nt][1];
            stg[(row + 8) * 132 + col] = acc[mi][nt][2];
            stg[(row + 8) * 132 + col + 1] = acc[mi][nt][3];
        }
    __syncthreads();
    #pragma unroll
    for (int r8 = 0; r8 < 8; r8++) {
        int row = wid + r8 * 8;
        float4 v = *reinterpret_cast<float4*>(stg + row * 132 + lane * 4);
        float vv[4] = {v.x, v.y, v.z, v.w};
        if (EPI == 1) {
            #pragma unroll
            for (int t = 0; t < 4; t++) { float r = fmaxf(vv[t], 0.f); vv[t] = r * r; }
        }
        if (EPI == 2) {
            float4 rv = *reinterpret_cast<const float4*>(
                Res + (size_t)bc * M * 512 + (size_t)(m0 + row) * 512 + n0 + lane * 4);
            vv[0] += rv.x; vv[1] += rv.y; vv[2] += rv.z; vv[3] += rv.w;
        }
        float4 o = {vv[0], vv[1], vv[2], vv[3]};
        *reinterpret_cast<float4*>(Cb + (size_t)(m0 + row) * 512 + n0 + lane * 4) = o;
    }
}

// ---------------- attention scores: S = scale * Q^T K ------------------------
__global__ void __launch_bounds__(256) attn_qk_mma(
    const float* __restrict__ Q, const float* __restrict__ Kt, float* __restrict__ S)
{
    __shared__ char sm[49152];
    uint32_t sb = smem_u32(sm);
    int tid = threadIdx.x, wid = tid >> 5, lane = tid & 31;
    int wm = wid >> 2, wn = wid & 3;
    int z = blockIdx.z, bc = z >> 3, hd = z & 7;
    int q0 = blockIdx.y * 64, k0 = blockIdx.x * 128;
    const float* Qb = Q + ((size_t)bc * 512 + hd * 64) * 512;
    const float* Kb = Kt + ((size_t)bc * 512 + hd * 64) * 512;
    float* Sb = S + (size_t)z * 262144;

    float acc[2][4][4] = {};
    tloadT<64>(sm, sm + 8192, Qb + q0, 512, tid);
    tloadT<128>(sm + 16384, sm + 32768, Kb + k0, 512, tid);
    __syncthreads();
    mma_chunk<4>(acc, sb, sb + 8192, sb + 16384, sb + 32768, wm, wn, lane);
    __syncthreads();
    float* stg = (float*)sm;
    #pragma unroll
    for (int mi = 0; mi < 2; mi++)
        #pragma unroll
        for (int nt = 0; nt < 4; nt++) {
            int row = wm * 32 + mi * 16 + (lane >> 2);
            int col = wn * 32 + nt * 8 + (lane & 3) * 2;
            stg[row * 132 + col] = acc[mi][nt][0];
            stg[row * 132 + col + 1] = acc[mi][nt][1];
            stg[(row + 8) * 132 + col] = acc[mi][nt][2];
            stg[(row + 8) * 132 + col + 1] = acc[mi][nt][3];
        }
    __syncthreads();
    const float scale = 0.044194173824159216f;  // 1/sqrt(512)
    #pragma unroll
    for (int r8 = 0; r8 < 8; r8++) {
        int row = wid + r8 * 8;
        float4 v = *reinterpret_cast<float4*>(stg + row * 132 + lane * 4);
        float4 o = {v.x * scale, v.y * scale, v.z * scale, v.w * scale};
        *reinterpret_cast<float4*>(Sb + (size_t)(q0 + row) * 512 + k0 + lane * 4) = o;
    }
}

// ---------------- attention output: O[d,q] = sum_k P[q,k] V[d,k] -------------
__global__ void __launch_bounds__(256) attn_pv_mma(
    const float* __restrict__ P, const float* __restrict__ V, float* __restrict__ O)
{
    __shared__ char sm[32768];
    uint32_t sb = smem_u32(sm);
    int tid = threadIdx.x, wid = tid >> 5, lane = tid & 31;
    int wm = wid >> 2, wn = wid & 3;
    int z = blockIdx.z, bc = z >> 3, hd = z & 7;
    int q0 = blockIdx.x * 64;
    const float* Pb = P + (size_t)z * 262144;
    const float* Vb = V + ((size_t)bc * 512 + hd * 64) * 512;
    float* Ob = O + ((size_t)bc * 512 + hd * 64) * 512;

    float acc[2][2][4] = {};
    for (int ch = 0; ch < 8; ch++) {
        __syncthreads();
        nload(sm, sm + 8192, Pb + (size_t)q0 * 512 + ch * 64, 512, 64, tid);
        nload(sm + 16384, sm + 24576, Vb + ch * 64, 512, 64, tid);
        __syncthreads();
        mma_chunk<2>(acc, sb, sb + 8192, sb + 16384, sb + 24576, wm, wn, lane);
    }
    __syncthreads();
    float* stg = (float*)sm;  // [q][d] stride 68
    #pragma unroll
    for (int mi = 0; mi < 2; mi++)
        #pragma unroll
        for (int nt = 0; nt < 2; nt++) {
            int row = wm * 32 + mi * 16 + (lane >> 2);
            int col = wn * 16 + nt * 8 + (lane & 3) * 2;
            stg[row * 68 + col] = acc[mi][nt][0];
            stg[row * 68 + col + 1] = acc[mi][nt][1];
            stg[(row + 8) * 68 + col] = acc[mi][nt][2];
            stg[(row + 8) * 68 + col + 1] = acc[mi][nt][3];
        }
    __syncthreads();
    #pragma unroll
    for (int i = 0; i < 4; i++) {
        int idx = tid + i * 256;
        int d = idx >> 4, qg = idx & 15;
        float4 o;
        o.x = stg[(qg * 4 + 0) * 68 + d];
        o.y = stg[(qg * 4 + 1) * 68 + d];
        o.z = stg[(qg * 4 + 2) * 68 + d];
        o.w = stg[(qg * 4 + 3) * 68 + d];
        *reinterpret_cast<float4*>(Ob + (size_t)d * 512 + q0 + qg * 4) = o;
    }
}

// ---------------- fused QKV channel-mix (+RoPE for Q,K) ----------------------
__global__ void __launch_bounds__(256) qkv_post(
    const float* __restrict__ Xall,
    const float* __restrict__ qdw, const float* __restrict__ kdw, const float* __restrict__ vdw,
    float* __restrict__ Q, float* __restrict__ K, float* __restrict__ V)
{
    int proj = blockIdx.y;
    const float* X = Xall + (size_t)proj * 1048576;
    const float* dwp = proj == 0 ? qdw : (proj == 1 ? kdw : vdw);
    float* Y = proj == 0 ? Q : (proj == 1 ? K : V);
    int idx = blockIdx.x * 256 + threadIdx.x;
    int w = idx & 511, fp = (idx >> 9) & 255, bd = idx >> 17;
    int b = bd >> 1, d = bd & 1;
    int f0 = fp * 2;
    size_t b0 = ((size_t)(b * 2) * 512 + f0) * 512 + w;
    float d0 = dwp[d * 2 + 0], d1 = dwp[d * 2 + 1];
    float v0 = d0 * X[b0] + d1 * X[b0 + 262144];
    float v1 = d0 * X[b0 + 512] + d1 * X[b0 + 512 + 262144];
    size_t o0 = ((size_t)bd * 512 + f0) * 512 + w;
    if (proj < 2) {
        int i = fp & 31;
        float inv = powf(10000.f, -(float)(2 * i) / 64.f);
        float sn, cs;
        sincosf((float)w * inv, &sn, &cs);
        Y[o0] = v0 * cs - v1 * sn;
        Y[o0 + 512] = v1 * cs + v0 * sn;
    } else {
        Y[o0] = v0;
        Y[o0 + 512] = v1;
    }
}

template<bool SQRELU, bool HASADD>
__global__ void __launch_bounds__(256) mix_k(
    const float* __restrict__ X, const float* __restrict__ dw,
    const float* __restrict__ Add, float* __restrict__ Y, int Fd)
{
    int idx = blockIdx.x * 256 + threadIdx.x;
    int w = idx & 511;
    int f = (idx >> 9) % Fd;
    int bd = idx / (512 * Fd);
    int b = bd >> 1, d = bd & 1;
    size_t base = ((size_t)(b * 2) * Fd + f) * 512 + w;
    float v = dw[d * 2 + 0] * X[base] + dw[d * 2 + 1] * X[base + (size_t)Fd * 512];
    if (SQRELU) { float r = fmaxf(v, 0.f); v = r * r; }
    if (HASADD) v += Add[idx];
    Y[idx] = v;
}

__global__ void frame_norm_k(
    const float* __restrict__ X, const float* __restrict__ gw,
    const float* __restrict__ gb, float* __restrict__ Y)
{
    int bc = blockIdx.y, c = bc & 1;
    int tx = threadIdx.x, ty = threadIdx.y;
    int w = blockIdx.x * 32 + tx;
    const float* Xb = X + (size_t)bc * 262144;
    float* Yb = Y + (size_t)bc * 262144;
    float sum = 0.f, sq = 0.f;
    for (int f = ty; f < 512; f += 8) {
        float v = Xb[(size_t)f * 512 + w];
        sum += v; sq += v * v;
    }
    __shared__ float ss[8][33], s2[8][33], smu[32], srs[32];
    ss[ty][tx] = sum; s2[ty][tx] = sq;
    __syncthreads();
    if (ty == 0) {
        for (int r = 1; r < 8; r++) { sum += ss[r][tx]; sq += s2[r][tx]; }
        float mu = sum * (1.f / 512.f);
        float var = sq * (1.f / 512.f) - mu * mu;
        smu[tx] = mu; srs[tx] = rsqrtf(var + EPSV);
    }
    __syncthreads();
    float mu = smu[tx], rs = srs[tx];
    for (int f = ty; f < 512; f += 8) {
        float v = Xb[(size_t)f * 512 + w];
        Yb[(size_t)f * 512 + w] = (v - mu) * rs * gw[c * 512 + f] + gb[c * 512 + f];
    }
}

__global__ void __launch_bounds__(256) softmax_rows_k(float* __restrict__ S)
{
    int row = blockIdx.x * 8 + (threadIdx.x >> 5);
    int lane = threadIdx.x & 31;
    float* p = S + (size_t)row * 512;
    float v[16];
    float mx = -1e30f;
    #pragma unroll
    for (int i = 0; i < 16; i++) { v[i] = p[lane + i * 32]; mx = fmaxf(mx, v[i]); }
    #pragma unroll
    for (int o = 16; o; o >>= 1) mx = fmaxf(mx, __shfl_xor_sync(0xffffffffu, mx, o));
    float sum = 0.f;
    #pragma unroll
    for (int i = 0; i < 16; i++) { v[i] = __expf(v[i] - mx); sum += v[i]; }
    #pragma unroll
    for (int o = 16; o; o >>= 1) sum += __shfl_xor_sync(0xffffffffu, sum, o);
    float inv = 1.f / sum;
    #pragma unroll
    for (int i = 0; i < 16; i++) p[lane + i * 32] = v[i] * inv;
}

// ---------------- host orchestration -----------------------------------------
extern "C" void kernel_launch(void* const* d_in, const int* in_sizes, int n_in,
                              void* d_out, int out_size)
{
    const float* x     = (const float*)d_in[0];
    const float* e1_pw = (const float*)d_in[1];
    const float* e1_dw = (const float*)d_in[2];
    const float* e2_pw = (const float*)d_in[3];
    const float* e2_dw = (const float*)d_in[4];
    const float* ei_pw = (const float*)d_in[5];
    const float* ei_dw = (const float*)d_in[6];
    const float* n1_w  = (const float*)d_in[7];
    const float* n1_b  = (const float*)d_in[8];
    const float* q_pw  = (const float*)d_in[9];
    const float* q_dw  = (const float*)d_in[10];
    const float* k_pw  = (const float*)d_in[11];
    const float* k_dw  = (const float*)d_in[12];
    const float* v_pw  = (const float*)d_in[13];
    const float* v_dw  = (const float*)d_in[14];
    const float* o_pw  = (const float*)d_in[15];
    const float* n2_w  = (const float*)d_in[16];
    const float* n2_b  = (const float*)d_in[17];
    const float* f1_pw = (const float*)d_in[18];
    const float* f2_pw = (const float*)d_in[19];
    const float* d1_pw = (const float*)d_in[20];
    const float* d1_dw = (const float*)d_in[21];
    const float* d2_pw = (const float*)d_in[22];
    const float* d2_dw = (const float*)d_in[23];
    const float* di_pw = (const float*)d_in[24];
    const float* di_dw = (const float*)d_in[25];
    float* out = (float*)d_out;
    (void)in_sizes; (void)n_in; (void)out_size;

    float *e, *h, *q, *k, *v, *big, *s;
    cudaGetSymbolAddress((void**)&e, g_e);
    cudaGetSymbolAddress((void**)&h, g_h);
    cudaGetSymbolAddress((void**)&q, g_q);
    cudaGetSymbolAddress((void**)&k, g_k);
    cudaGetSymbolAddress((void**)&v, g_v);
    cudaGetSymbolAddress((void**)&big, g_big);
    cudaGetSymbolAddress((void**)&s, g_s);

    dim3 lnG(16, 4), lnB(32, 8);
    float* tmp = s;  // reuse attention scratch outside attention

    // encoder frame_block
    gemm_mma<0><<<dim3(4, 8, 4), 256>>>(e1_pw, e1_pw, e1_pw, x, nullptr, tmp, 512, 1024);
    mix_k<true, false><<<4096, 256>>>(tmp, e1_dw, nullptr, h, 512);
    gemm_mma<0><<<dim3(4, 8, 4), 256>>>(e2_pw, e2_pw, e2_pw, h, nullptr, tmp, 512, 512);
    mix_k<false, false><<<4096, 256>>>(tmp, e2_dw, nullptr, q, 512);
    gemm_mma<0><<<dim3(4, 8, 4), 256>>>(ei_pw, ei_pw, ei_pw, x, nullptr, tmp, 512, 1024);
    mix_k<false, true><<<4096, 256>>>(tmp, ei_dw, q, e, 512);

    for (int i = 0; i < NLAYER; i++) {
        const float* qpw = q_pw + (size_t)i * 524288;
        const float* kpw = k_pw + (size_t)i * 524288;
        const float* vpw = v_pw + (size_t)i * 524288;
        const float* opw = o_pw + (size_t)i * 524288;
        const float* f1w = f1_pw + (size_t)i * 2097152;
        const float* f2w = f2_pw + (size_t)i * 2097152;

        frame_norm_k<<<lnG, lnB>>>(e, n1_w + (size_t)i * 1024, n1_b + (size_t)i * 1024, h);
        gemm_mma<0><<<dim3(4, 8, 12), 256>>>(qpw, kpw, vpw, h, nullptr, big, 512, 512);
        qkv_post<<<dim3(2048, 3), 256>>>(big, q_dw + i * 4, k_dw + i * 4, v_dw + i * 4, q, k, v);
        attn_qk_mma<<<dim3(4, 8, 32), 256>>>(q, k, s);
        softmax_rows_k<<<2048, 256>>>(s);
        attn_pv_mma<<<dim3(8, 1, 32), 256>>>(s, v, h);
        gemm_mma<2><<<dim3(4, 8, 4), 256>>>(opw, opw, opw, h, e, e, 512, 512);

        frame_norm_k<<<lnG, lnB>>>(e, n2_w + (size_t)i * 1024, n2_b + (size_t)i * 1024, h);
        gemm_mma<1><<<dim3(4, 32, 4), 256>>>(f1w, f1w, f1w, h, nullptr, big, 2048, 512);
        gemm_mma<2><<<dim3(4, 8, 4), 256>>>(f2w, f2w, f2w, big, e, e, 512, 2048);
    }

    // decoder frame_block
    float* ta = big;
    float* tb = s;
    float* tz = s + 2097152;
    gemm_mma<0><<<dim3(4, 16, 4), 256>>>(d1_pw, d1_pw, d1_pw, e, nullptr, ta, 1024, 512);
    mix_k<true, false><<<8192, 256>>>(ta, d1_dw, nullptr, tb, 1024);
    gemm_mma<0><<<dim3(4, 16, 4), 256>>>(d2_pw, d2_pw, d2_pw, tb, nullptr, ta, 1024, 1024);
    mix_k<false, false><<<8192, 256>>>(ta, d2_dw, nullptr, tz, 1024);
    gemm_mma<0><<<dim3(4, 16, 4), 256>>>(di_pw, di_pw, di_pw, e, nullptr, ta, 1024, 512);
    mix_k<false, true><<<8192, 256>>>(ta, di_dw, tz, out, 1024);
}

// round 7
// speedup vs baseline: 2.7847x; 2.1913x over previous
#include <cuda_runtime.h>
#include <cuda_bf16.h>
#include <math.h>
#include <stdint.h>

#define NLAYER 12
#define EPSV 1e-5f
typedef unsigned short u16;

// ---------------- f32 scratch ------------------------------------------------
__device__ float g_e  [1048576];
__device__ float g_h  [1048576];
__device__ float g_q  [1048576];
__device__ float g_k  [1048576];
__device__ float g_big[4194304];
__device__ float g_s  [8388608];

// ---------------- bf16 hi/lo buffers -----------------------------------------
#define OFF_E1 0L
#define OFF_E2 1048576L
#define OFF_EI 1572864L
#define OFF_Q  2621440L
#define OFF_K  8912896L
#define OFF_V  15204352L
#define OFF_O  21495808L
#define OFF_F1 27787264L
#define OFF_F2 52953088L
#define OFF_D1 78118912L
#define OFF_D2 79167488L
#define OFF_DI 81264640L
#define W_TOT  82313216L
__device__ u16 g_wh[W_TOT];
__device__ u16 g_wl[W_TOT];
__device__ u16 g_ath[4194304], g_atl[4194304];   // xT / bigT / decT
__device__ u16 g_hth[1048576], g_htl[1048576];   // hT / eT
__device__ u16 g_qth[1048576], g_qtl[1048576];
__device__ u16 g_kth[1048576], g_ktl[1048576];
__device__ u16 g_vh [1048576], g_vl [1048576];
__device__ u16 g_ph [8388608], g_pl [8388608];
__device__ u16 g_oth[1048576], g_otl[1048576];

// ---------------- helpers ----------------------------------------------------
__device__ __forceinline__ uint32_t smem_u32(const void* p) {
    uint32_t a;
    asm("{ .reg .u64 t; cvta.to.shared.u64 t, %1; cvt.u32.u64 %0, t; }" : "=r"(a) : "l"(p));
    return a;
}
#define SWZ(x) ((x) ^ (((x) >> 3) & 0x70))

__device__ __forceinline__ void cp16(uint32_t d, const void* g) {
    asm volatile("cp.async.cg.shared.global [%0], [%1], 16;" :: "r"(d), "l"(g));
}
__device__ __forceinline__ void cp_commit() { asm volatile("cp.async.commit_group;"); }
template<int N> __device__ __forceinline__ void cp_wait() {
    asm volatile("cp.async.wait_group %0;" :: "n"(N));
}
__device__ __forceinline__ void ldsm4(uint32_t* r, uint32_t a) {
    asm volatile("ldmatrix.sync.aligned.m8n8.x4.shared.b16 {%0,%1,%2,%3}, [%4];"
                 : "=r"(r[0]), "=r"(r[1]), "=r"(r[2]), "=r"(r[3]) : "r"(a));
}
__device__ __forceinline__ void mma16816(float* c, const uint32_t* a, const uint32_t* b) {
    asm volatile(
        "mma.sync.aligned.m16n8k16.row.col.f32.bf16.bf16.f32 "
        "{%0,%1,%2,%3}, {%4,%5,%6,%7}, {%8,%9}, {%0,%1,%2,%3};"
        : "+f"(c[0]), "+f"(c[1]), "+f"(c[2]), "+f"(c[3])
        : "r"(a[0]), "r"(a[1]), "r"(a[2]), "r"(a[3]), "r"(b[0]), "r"(b[1]));
}
__device__ __forceinline__ void splt(float v, u16& h, u16& l) {
    __nv_bfloat16 hb = __float2bfloat16(v);
    h = __bfloat16_as_ushort(hb);
    l = __bfloat16_as_ushort(__float2bfloat16(v - __bfloat162float(hb)));
}

// warp computes 32m x (NT*8)n over one K-chunk of 64, 3-term split (verified R6)
template<int NT>
__device__ __forceinline__ void mma_chunk(
    float (&acc)[2][NT][4], uint32_t aHi, uint32_t aLo, uint32_t bHi, uint32_t bLo,
    int wm, int wn, int lane)
{
    int la = lane & 7, j = lane >> 3;
    #pragma unroll
    for (int ks = 0; ks < 4; ks++) {
        uint32_t ah[2][4], al[2][4];
        #pragma unroll
        for (int mi = 0; mi < 2; mi++) {
            uint32_t off = SWZ((uint32_t)((wm * 32 + mi * 16 + ((j & 1) << 3) + la) * 128 + ks * 32 + ((j >> 1) << 4)));
            ldsm4(ah[mi], aHi + off);
            ldsm4(al[mi], aLo + off);
        }
        uint32_t bh[NT][2], bl[NT][2];
        #pragma unroll
        for (int nt = 0; nt < NT; nt += 2) {
            uint32_t off = SWZ((uint32_t)((wn * NT * 8 + nt * 8 + ((j >> 1) << 3) + la) * 128 + ks * 32 + ((j & 1) << 4)));
            uint32_t t[4];
            ldsm4(t, bHi + off);
            bh[nt][0] = t[0]; bh[nt][1] = t[1]; bh[nt + 1][0] = t[2]; bh[nt + 1][1] = t[3];
            ldsm4(t, bLo + off);
            bl[nt][0] = t[0]; bl[nt][1] = t[1]; bl[nt + 1][0] = t[2]; bl[nt + 1][1] = t[3];
        }
        #pragma unroll
        for (int mi = 0; mi < 2; mi++)
            #pragma unroll
            for (int nt = 0; nt < NT; nt++) {
                mma16816(acc[mi][nt], ah[mi], bh[nt]);
                mma16816(acc[mi][nt], ah[mi], bl[nt]);
                mma16816(acc[mi][nt], al[mi], bh[nt]);
            }
    }
}

// ---------------- one-time weight split --------------------------------------
__global__ void __launch_bounds__(256) split_w(
    const float* p0, const float* p1, const float* p2, const float* p3,
    const float* p4, const float* p5, const float* p6, const float* p7,
    const float* p8, const float* p9, const float* p10, const float* p11)
{
    const long offs[12] = {OFF_E1, OFF_E2, OFF_EI, OFF_Q, OFF_K, OFF_V,
                           OFF_O, OFF_F1, OFF_F2, OFF_D1, OFF_D2, OFF_DI};
    const float* ptrs[12] = {p0, p1, p2, p3, p4, p5, p6, p7, p8, p9, p10, p11};
    long base = ((long)blockIdx.x * 256 + threadIdx.x) * 16;
    if (base >= W_TOT) return;
    int seg = 0;
    #pragma unroll
    for (int i = 1; i < 12; i++) if (base >= offs[i]) seg = i;
    const float* src = ptrs[seg] + (base - offs[seg]);
    u16 hb[16], lb[16];
    #pragma unroll
    for (int t = 0; t < 16; t += 4) {
        float4 x = *reinterpret_cast<const float4*>(src + t);
        splt(x.x, hb[t], lb[t]); splt(x.y, hb[t+1], lb[t+1]);
        splt(x.z, hb[t+2], lb[t+2]); splt(x.w, hb[t+3], lb[t+3]);
    }
    uint4* dh = reinterpret_cast<uint4*>(&g_wh[base]);
    uint4* dl = reinterpret_cast<uint4*>(&g_wl[base]);
    dh[0] = ((uint4*)hb)[0]; dh[1] = ((uint4*)hb)[1];
    dl[0] = ((uint4*)lb)[0]; dl[1] = ((uint4*)lb)[1];
}

// ---------------- transpose-split: X (z,R,512) f32 -> T (z,512,R) bf16 -------
__global__ void __launch_bounds__(256) tsplit(
    const float* __restrict__ X, u16* __restrict__ Th, u16* __restrict__ Tl, int R)
{
    __shared__ float s[64][65];
    int tid = threadIdx.x;
    int z = blockIdx.z, f0 = blockIdx.y * 64, w0 = blockIdx.x * 64;
    const float* Xb = X + ((size_t)z * R + f0) * 512 + w0;
    for (int it = tid; it < 1024; it += 256) {
        int r = it >> 4, cg = it & 15;
        float4 v = *reinterpret_cast<const float4*>(Xb + (size_t)r * 512 + cg * 4);
        s[r][cg * 4 + 0] = v.x; s[r][cg * 4 + 1] = v.y;
        s[r][cg * 4 + 2] = v.z; s[r][cg * 4 + 3] = v.w;
    }
    __syncthreads();
    for (int it = tid; it < 512; it += 256) {
        int w = it >> 3, cg = it & 7;
        u16 hb[8], lb[8];
        #pragma unroll
        for (int j = 0; j < 8; j++) splt(s[cg * 8 + j][w], hb[j], lb[j]);
        size_t o = ((size_t)z * 512 + w0 + w) * R + f0 + cg * 8;
        *reinterpret_cast<uint4*>(Th + o) = *reinterpret_cast<uint4*>(hb);
        *reinterpret_cast<uint4*>(Tl + o) = *reinterpret_cast<uint4*>(lb);
    }
}

// ---------------- pipelined bf16 GEMM: C = W[c] @ X[bc] ----------------------
// A: (M,K) row-major bf16 hi/lo ; B: (512 n, K) n-major bf16 hi/lo
// OUT: 0 = f32 C ; 2 = f32 C + residual ; 3 = sqrelu, write CT bf16 hi/lo
template<int OUT>
__global__ void __launch_bounds__(256) gemm_bb(
    const u16* __restrict__ Ah, const u16* __restrict__ Al,
    const u16* __restrict__ Bh, const u16* __restrict__ Bl,
    const float* __restrict__ Res, float* __restrict__ C,
    u16* __restrict__ CTh, u16* __restrict__ CTl,
    int M, int K, long projStride)
{
    extern __shared__ char sm[];
    uint32_t sb = smem_u32(sm);
    int tid = threadIdx.x, wid = tid >> 5, lane = tid & 31;
    int wm = wid >> 2, wn = wid & 3;
    int proj = blockIdx.z >> 2, bc = blockIdx.z & 3, c = bc & 1;
    const u16* Ab_h = Ah + proj * projStride + (size_t)c * M * K;
    const u16* Ab_l = Al + proj * projStride + (size_t)c * M * K;
    const u16* Bb_h = Bh + (size_t)bc * 512 * K;
    const u16* Bb_l = Bl + (size_t)bc * 512 * K;
    int m0 = blockIdx.y * 64, n0 = blockIdx.x * 128;

    auto load_stage = [&](int ch, int s) {
        uint32_t st = sb + s * 49152;
        const u16* ah = Ab_h + (size_t)m0 * K + ch * 64;
        const u16* al = Ab_l + (size_t)m0 * K + ch * 64;
        for (int it = tid; it < 512; it += 256) {
            int r = it >> 3, cg = it & 7;
            uint32_t o = SWZ((uint32_t)(r * 128 + cg * 16));
            size_t gof = (size_t)r * K + cg * 8;
            cp16(st + o, ah + gof);
            cp16(st + 8192 + o, al + gof);
        }
        const u16* bh = Bb_h + (size_t)n0 * K + ch * 64;
        const u16* bl = Bb_l + (size_t)n0 * K + ch * 64;
        for (int it = tid; it < 1024; it += 256) {
            int r = it >> 3, cg = it & 7;
            uint32_t o = SWZ((uint32_t)(r * 128 + cg * 16));
            size_t gof = (size_t)r * K + cg * 8;
            cp16(st + 16384 + o, bh + gof);
            cp16(st + 32768 + o, bl + gof);
        }
    };

    float acc[2][4][4] = {};
    int NC = K >> 6;
    load_stage(0, 0); cp_commit();
    for (int ch = 0; ch < NC; ch++) {
        if (ch + 1 < NC) { load_stage(ch + 1, (ch + 1) & 1); cp_commit(); cp_wait<1>(); }
        else cp_wait<0>();
        __syncthreads();
        uint32_t st = sb + (ch & 1) * 49152;
        mma_chunk<4>(acc, st, st + 8192, st + 16384, st + 32768, wm, wn, lane);
        __syncthreads();
    }

    float* stg = (float*)sm;  // 64 x 132
    #pragma unroll
    for (int mi = 0; mi < 2; mi++)
        #pragma unroll
        for (int nt = 0; nt < 4; nt++) {
            int row = wm * 32 + mi * 16 + (lane >> 2);
            int col = wn * 32 + nt * 8 + (lane & 3) * 2;
            stg[row * 132 + col] = acc[mi][nt][0];
            stg[row * 132 + col + 1] = acc[mi][nt][1];
            stg[(row + 8) * 132 + col] = acc[mi][nt][2];
            stg[(row + 8) * 132 + col + 1] = acc[mi][nt][3];
        }
    __syncthreads();

    if (OUT == 3) {
        int j = tid >> 1, msel = tid & 1;
        u16 hb[32], lb[32];
        #pragma unroll
        for (int i = 0; i < 32; i++) {
            float v = stg[(msel * 32 + i) * 132 + j];
            float r = fmaxf(v, 0.f); v = r * r;
            splt(v, hb[i], lb[i]);
        }
        size_t o = ((size_t)bc * 512 + n0 + j) * (size_t)M + m0 + msel * 32;
        #pragma unroll
        for (int t = 0; t < 4; t++) {
            reinterpret_cast<uint4*>(CTh + o)[t] = ((uint4*)hb)[t];
            reinterpret_cast<uint4*>(CTl + o)[t] = ((uint4*)lb)[t];
        }
    } else {
        float* Cb = C + (size_t)(proj * 4 + bc) * M * 512;
        #pragma unroll
        for (int r8 = 0; r8 < 8; r8++) {
            int row = wid + r8 * 8;
            float4 v = *reinterpret_cast<float4*>(stg + row * 132 + lane * 4);
            float vv[4] = {v.x, v.y, v.z, v.w};
            if (OUT == 2) {
                float4 rv = *reinterpret_cast<const float4*>(
                    Res + (size_t)bc * M * 512 + (size_t)(m0 + row) * 512 + n0 + lane * 4);
                vv[0] += rv.x; vv[1] += rv.y; vv[2] += rv.z; vv[3] += rv.w;
            }
            float4 ov = {vv[0], vv[1], vv[2], vv[3]};
            *reinterpret_cast<float4*>(Cb + (size_t)(m0 + row) * 512 + n0 + lane * 4) = ov;
        }
    }
}

// ---------------- attention scores: S = scale * QT @ KT^T --------------------
__global__ void __launch_bounds__(256) attn_qk_bb(
    const u16* __restrict__ QTh, const u16* __restrict__ QTl,
    const u16* __restrict__ KTh, const u16* __restrict__ KTl,
    float* __restrict__ S)
{
    __shared__ char sm[49152];
    uint32_t sb = smem_u32(sm);
    int tid = threadIdx.x, wid = tid >> 5, lane = tid & 31;
    int wm = wid >> 2, wn = wid & 3;
    int z = blockIdx.z, bc = z >> 3, hd = z & 7;
    int q0 = blockIdx.y * 64, k0 = blockIdx.x * 128;
    size_t qbase = ((size_t)bc * 512 + q0) * 512 + hd * 64;
    size_t kbase = ((size_t)bc * 512 + k0) * 512 + hd * 64;

    for (int it = tid; it < 512; it += 256) {
        int r = it >> 3, cg = it & 7;
        uint32_t o = SWZ((uint32_t)(r * 128 + cg * 16));
        cp16(sb + o, QTh + qbase + (size_t)r * 512 + cg * 8);
        cp16(sb + 8192 + o, QTl + qbase + (size_t)r * 512 + cg * 8);
    }
    for (int it = tid; it < 1024; it += 256) {
        int r = it >> 3, cg = it & 7;
        uint32_t o = SWZ((uint32_t)(r * 128 + cg * 16));
        cp16(sb + 16384 + o, KTh + kbase + (size_t)r * 512 + cg * 8);
        cp16(sb + 32768 + o, KTl + kbase + (size_t)r * 512 + cg * 8);
    }
    cp_commit(); cp_wait<0>();
    __syncthreads();

    float acc[2][4][4] = {};
    mma_chunk<4>(acc, sb, sb + 8192, sb + 16384, sb + 32768, wm, wn, lane);
    __syncthreads();
    float* stg = (float*)sm;
    #pragma unroll
    for (int mi = 0; mi < 2; mi++)
        #pragma unroll
        for (int nt = 0; nt < 4; nt++) {
            int row = wm * 32 + mi * 16 + (lane >> 2);
            int col = wn * 32 + nt * 8 + (lane & 3) * 2;
            stg[row * 132 + col] = acc[mi][nt][0];
            stg[row * 132 + col + 1] = acc[mi][nt][1];
            stg[(row + 8) * 132 + col] = acc[mi][nt][2];
            stg[(row + 8) * 132 + col + 1] = acc[mi][nt][3];
        }
    __syncthreads();
    const float scale = 0.044194173824159216f;  // 1/sqrt(512)
    float* Sb = S + (size_t)z * 262144;
    #pragma unroll
    for (int r8 = 0; r8 < 8; r8++) {
        int row = wid + r8 * 8;
        float4 v = *reinterpret_cast<float4*>(stg + row * 132 + lane * 4);
        float4 o = {v.x * scale, v.y * scale, v.z * scale, v.w * scale};
        *reinterpret_cast<float4*>(Sb + (size_t)(q0 + row) * 512 + k0 + lane * 4) = o;
    }
}

// ---------------- attention output: OT[q,d] = sum_k P[q,k] V[d,k] ------------
__global__ void __launch_bounds__(256) attn_pv_bb(
    const u16* __restrict__ Ph, const u16* __restrict__ Pl,
    const u16* __restrict__ Vh, const u16* __restrict__ Vl,
    u16* __restrict__ OTh, u16* __restrict__ OTl)
{
    extern __shared__ char sm[];
    uint32_t sb = smem_u32(sm);
    int tid = threadIdx.x, wid = tid >> 5, lane = tid & 31;
    int wm = wid >> 2, wn = wid & 3;
    int z = blockIdx.z, bc = z >> 3, hd = z & 7;
    int q0 = blockIdx.x * 64;
    size_t pbase = ((size_t)z * 512 + q0) * 512;
    size_t vbase = ((size_t)bc * 512 + hd * 64) * 512;

    auto load_stage = [&](int ch, int s) {
        uint32_t st = sb + s * 32768;
        for (int it = tid; it < 512; it += 256) {
            int r = it >> 3, cg = it & 7;
            uint32_t o = SWZ((uint32_t)(r * 128 + cg * 16));
            size_t pof = pbase + (size_t)r * 512 + ch * 64 + cg * 8;
            size_t vof = vbase + (size_t)r * 512 + ch * 64 + cg * 8;
            cp16(st + o, Ph + pof);
            cp16(st + 8192 + o, Pl + pof);
            cp16(st + 16384 + o, Vh + vof);
            cp16(st + 24576 + o, Vl + vof);
        }
    };

    float acc[2][2][4] = {};
    load_stage(0, 0); cp_commit();
    for (int ch = 0; ch < 8; ch++) {
        if (ch + 1 < 8) { load_stage(ch + 1, (ch + 1) & 1); cp_commit(); cp_wait<1>(); }
        else cp_wait<0>();
        __syncthreads();
        uint32_t st = sb + (ch & 1) * 32768;
        mma_chunk<2>(acc, st, st + 8192, st + 16384, st + 24576, wm, wn, lane);
        __syncthreads();
    }
    float* stg = (float*)sm;  // 64 x 68
    #pragma unroll
    for (int mi = 0; mi < 2; mi++)
        #pragma unroll
        for (int nt = 0; nt < 2; nt++) {
            int row = wm * 32 + mi * 16 + (lane >> 2);
            int col = wn * 16 + nt * 8 + (lane & 3) * 2;
            stg[row * 68 + col] = acc[mi][nt][0];
            stg[row * 68 + col + 1] = acc[mi][nt][1];
            stg[(row + 8) * 68 + col] = acc[mi][nt][2];
            stg[(row + 8) * 68 + col + 1] = acc[mi][nt][3];
        }
    __syncthreads();
    int row = tid >> 2, dseg = tid & 3;
    u16 hb[16], lb[16];
    #pragma unroll
    for (int j = 0; j < 16; j++) splt(stg[row * 68 + dseg * 16 + j], hb[j], lb[j]);
    size_t o = ((size_t)bc * 512 + q0 + row) * 512 + hd * 64 + dseg * 16;
    reinterpret_cast<uint4*>(OTh + o)[0] = ((uint4*)hb)[0];
    reinterpret_cast<uint4*>(OTh + o)[1] = ((uint4*)hb)[1];
    reinterpret_cast<uint4*>(OTl + o)[0] = ((uint4*)lb)[0];
    reinterpret_cast<uint4*>(OTl + o)[1] = ((uint4*)lb)[1];
}

// ---------------- QKV channel-mix (+RoPE Q,K f32; V -> bf16 hi/lo) -----------
__global__ void __launch_bounds__(256) qkv_post(
    const float* __restrict__ Xall,
    const float* __restrict__ qdw, const float* __restrict__ kdw, const float* __restrict__ vdw,
    float* __restrict__ Q, float* __restrict__ K, u16* __restrict__ Vh, u16* __restrict__ Vl)
{
    int proj = blockIdx.y;
    const float* X = Xall + (size_t)proj * 1048576;
    const float* dwp = proj == 0 ? qdw : (proj == 1 ? kdw : vdw);
    int idx = blockIdx.x * 256 + threadIdx.x;
    int w = idx & 511, fp = (idx >> 9) & 255, bd = idx >> 17;
    int b = bd >> 1, d = bd & 1;
    int f0 = fp * 2;
    size_t b0 = ((size_t)(b * 2) * 512 + f0) * 512 + w;
    float d0 = dwp[d * 2 + 0], d1 = dwp[d * 2 + 1];
    float v0 = d0 * X[b0] + d1 * X[b0 + 262144];
    float v1 = d0 * X[b0 + 512] + d1 * X[b0 + 512 + 262144];
    size_t o0 = ((size_t)bd * 512 + f0) * 512 + w;
    if (proj < 2) {
        int i = fp & 31;
        float inv = powf(10000.f, -(float)(2 * i) / 64.f);
        float sn, cs;
        sincosf((float)w * inv, &sn, &cs);
        float* Y = proj == 0 ? Q : K;
        Y[o0] = v0 * cs - v1 * sn;
        Y[o0 + 512] = v1 * cs + v0 * sn;
    } else {
        u16 h0, l0, h1, l1;
        splt(v0, h0, l0); splt(v1, h1, l1);
        Vh[o0] = h0; Vl[o0] = l0;
        Vh[o0 + 512] = h1; Vl[o0 + 512] = l1;
    }
}

// ---------------- channel mix (enc/dec, f32) ---------------------------------
template<bool SQRELU, bool HASADD>
__global__ void __launch_bounds__(256) mix_k(
    const float* __restrict__ X, const float* __restrict__ dw,
    const float* __restrict__ Add, float* __restrict__ Y, int Fd)
{
    int idx = blockIdx.x * 256 + threadIdx.x;
    int w = idx & 511;
    int f = (idx >> 9) % Fd;
    int bd = idx / (512 * Fd);
    int b = bd >> 1, d = bd & 1;
    size_t base = ((size_t)(b * 2) * Fd + f) * 512 + w;
    float v = dw[d * 2 + 0] * X[base] + dw[d * 2 + 1] * X[base + (size_t)Fd * 512];
    if (SQRELU) { float r = fmaxf(v, 0.f); v = r * r; }
    if (HASADD) v += Add[idx];
    Y[idx] = v;
}

// ---------------- frame_norm (f32) -------------------------------------------
__global__ void frame_norm_k(
    const float* __restrict__ X, const float* __restrict__ gw,
    const float* __restrict__ gb, float* __restrict__ Y)
{
    int bc = blockIdx.y, c = bc & 1;
    int tx = threadIdx.x, ty = threadIdx.y;
    int w = blockIdx.x * 32 + tx;
    const float* Xb = X + (size_t)bc * 262144;
    float* Yb = Y + (size_t)bc * 262144;
    float sum = 0.f, sq = 0.f;
    for (int f = ty; f < 512; f += 8) {
        float v = Xb[(size_t)f * 512 + w];
        sum += v; sq += v * v;
    }
    __shared__ float ss[8][33], s2[8][33], smu[32], srs[32];
    ss[ty][tx] = sum; s2[ty][tx] = sq;
    __syncthreads();
    if (ty == 0) {
        for (int r = 1; r < 8; r++) { sum += ss[r][tx]; sq += s2[r][tx]; }
        float mu = sum * (1.f / 512.f);
        float var = sq * (1.f / 512.f) - mu * mu;
        smu[tx] = mu; srs[tx] = rsqrtf(var + EPSV);
    }
    __syncthreads();
    float mu = smu[tx], rs = srs[tx];
    for (int f = ty; f < 512; f += 8) {
        float v = Xb[(size_t)f * 512 + w];
        Yb[(size_t)f * 512 + w] = (v - mu) * rs * gw[c * 512 + f] + gb[c * 512 + f];
    }
}

// ---------------- softmax: S f32 -> P bf16 hi/lo -----------------------------
__global__ void __launch_bounds__(256) softmax_split(
    const float* __restrict__ S, u16* __restrict__ Ph, u16* __restrict__ Pl)
{
    int row = blockIdx.x * 8 + (threadIdx.x >> 5);
    int lane = threadIdx.x & 31;
    const float* p = S + (size_t)row * 512 + lane * 16;
    float v[16];
    #pragma unroll
    for (int g = 0; g < 4; g++) {
        float4 x = *reinterpret_cast<const float4*>(p + g * 4);
        v[g*4] = x.x; v[g*4+1] = x.y; v[g*4+2] = x.z; v[g*4+3] = x.w;
    }
    float mx = -1e30f;
    #pragma unroll
    for (int i = 0; i < 16; i++) mx = fmaxf(mx, v[i]);
    #pragma unroll
    for (int o = 16; o; o >>= 1) mx = fmaxf(mx, __shfl_xor_sync(0xffffffffu, mx, o));
    float sum = 0.f;
    #pragma unroll
    for (int i = 0; i < 16; i++) { v[i] = __expf(v[i] - mx); sum += v[i]; }
    #pragma unroll
    for (int o = 16; o; o >>= 1) sum += __shfl_xor_sync(0xffffffffu, sum, o);
    float inv = 1.f / sum;
    u16 hb[16], lb[16];
    #pragma unroll
    for (int i = 0; i < 16; i++) splt(v[i] * inv, hb[i], lb[i]);
    size_t o = (size_t)row * 512 + lane * 16;
    reinterpret_cast<uint4*>(Ph + o)[0] = ((uint4*)hb)[0];
    reinterpret_cast<uint4*>(Ph + o)[1] = ((uint4*)hb)[1];
    reinterpret_cast<uint4*>(Pl + o)[0] = ((uint4*)lb)[0];
    reinterpret_cast<uint4*>(Pl + o)[1] = ((uint4*)lb)[1];
}

// ---------------- host ---------------------------------------------------------
extern "C" void kernel_launch(void* const* d_in, const int* in_sizes, int n_in,
                              void* d_out, int out_size)
{
    const float* x     = (const float*)d_in[0];
    const float* e1_pw = (const float*)d_in[1];
    const float* e1_dw = (const float*)d_in[2];
    const float* e2_pw = (const float*)d_in[3];
    const float* e2_dw = (const float*)d_in[4];
    const float* ei_pw = (const float*)d_in[5];
    const float* ei_dw = (const float*)d_in[6];
    const float* n1_w  = (const float*)d_in[7];
    const float* n1_b  = (const float*)d_in[8];
    const float* q_dw  = (const float*)d_in[10];
    const float* k_dw  = (const float*)d_in[12];
    const float* v_dw  = (const float*)d_in[14];
    const float* n2_w  = (const float*)d_in[16];
    const float* n2_b  = (const float*)d_in[17];
    const float* d1_dw = (const float*)d_in[21];
    const float* d2_dw = (const float*)d_in[23];
    const float* di_dw = (const float*)d_in[25];
    float* out = (float*)d_out;
    (void)in_sizes; (void)n_in; (void)out_size;

    float *e, *h, *q, *k, *big, *s;
    cudaGetSymbolAddress((void**)&e, g_e);
    cudaGetSymbolAddress((void**)&h, g_h);
    cudaGetSymbolAddress((void**)&q, g_q);
    cudaGetSymbolAddress((void**)&k, g_k);
    cudaGetSymbolAddress((void**)&big, g_big);
    cudaGetSymbolAddress((void**)&s, g_s);
    u16 *wh, *wl, *ath, *atl, *hth, *htl, *qth, *qtl, *kth, *ktl, *vh, *vl, *ph, *pl, *oth, *otl;
    cudaGetSymbolAddress((void**)&wh, g_wh);   cudaGetSymbolAddress((void**)&wl, g_wl);
    cudaGetSymbolAddress((void**)&ath, g_ath); cudaGetSymbolAddress((void**)&atl, g_atl);
    cudaGetSymbolAddress((void**)&hth, g_hth); cudaGetSymbolAddress((void**)&htl, g_htl);
    cudaGetSymbolAddress((void**)&qth, g_qth); cudaGetSymbolAddress((void**)&qtl, g_qtl);
    cudaGetSymbolAddress((void**)&kth, g_kth); cudaGetSymbolAddress((void**)&ktl, g_ktl);
    cudaGetSymbolAddress((void**)&vh, g_vh);   cudaGetSymbolAddress((void**)&vl, g_vl);
    cudaGetSymbolAddress((void**)&ph, g_ph);   cudaGetSymbolAddress((void**)&pl, g_pl);
    cudaGetSymbolAddress((void**)&oth, g_oth); cudaGetSymbolAddress((void**)&otl, g_otl);

    const int SMG = 98304, SMPV = 65536;
    cudaFuncSetAttribute(gemm_bb<0>, cudaFuncAttributeMaxDynamicSharedMemorySize, SMG);
    cudaFuncSetAttribute(gemm_bb<2>, cudaFuncAttributeMaxDynamicSharedMemorySize, SMG);
    cudaFuncSetAttribute(gemm_bb<3>, cudaFuncAttributeMaxDynamicSharedMemorySize, SMG);
    cudaFuncSetAttribute(attn_pv_bb, cudaFuncAttributeMaxDynamicSharedMemorySize, SMPV);

    dim3 lnG(16, 4), lnB(32, 8);
    dim3 tsG512(8, 8, 4), tsG1024(8, 16, 4);

    split_w<<<20096, 256>>>(e1_pw, e2_pw, ei_pw,
        (const float*)d_in[9], (const float*)d_in[11], (const float*)d_in[13],
        (const float*)d_in[15], (const float*)d_in[18], (const float*)d_in[19],
        (const float*)d_in[20], (const float*)d_in[22], (const float*)d_in[24]);

    // encoder
    tsplit<<<tsG1024, 256>>>(x, ath, atl, 1024);
    gemm_bb<0><<<dim3(4, 8, 4), 256, SMG>>>(wh + OFF_E1, wl + OFF_E1, ath, atl, nullptr, big, nullptr, nullptr, 512, 1024, 0);
    mix_k<true, false><<<4096, 256>>>(big, e1_dw, nullptr, q, 512);
    tsplit<<<tsG512, 256>>>(q, hth, htl, 512);
    gemm_bb<0><<<dim3(4, 8, 4), 256, SMG>>>(wh + OFF_E2, wl + OFF_E2, hth, htl, nullptr, big, nullptr, nullptr, 512, 512, 0);
    mix_k<false, false><<<4096, 256>>>(big, e2_dw, nullptr, k, 512);
    gemm_bb<0><<<dim3(4, 8, 4), 256, SMG>>>(wh + OFF_EI, wl + OFF_EI, ath, atl, nullptr, big, nullptr, nullptr, 512, 1024, 0);
    mix_k<false, true><<<4096, 256>>>(big, ei_dw, k, e, 512);

    for (int i = 0; i < NLAYER; i++) {
        long lw = (long)i * 524288;
        frame_norm_k<<<lnG, lnB>>>(e, n1_w + (size_t)i * 1024, n1_b + (size_t)i * 1024, h);
        tsplit<<<tsG512, 256>>>(h, hth, htl, 512);
        gemm_bb<0><<<dim3(4, 8, 12), 256, SMG>>>(wh + OFF_Q + lw, wl + OFF_Q + lw, hth, htl,
                                                 nullptr, big, nullptr, nullptr, 512, 512, OFF_K - OFF_Q);
        qkv_post<<<dim3(2048, 3), 256>>>(big, q_dw + i * 4, k_dw + i * 4, v_dw + i * 4, q, k, vh, vl);
        tsplit<<<tsG512, 256>>>(q, qth, qtl, 512);
        tsplit<<<tsG512, 256>>>(k, kth, ktl, 512);
        attn_qk_bb<<<dim3(4, 8, 32), 256>>>(qth, qtl, kth, ktl, s);
        softmax_split<<<2048, 256>>>(s, ph, pl);
        attn_pv_bb<<<dim3(8, 1, 32), 256, SMPV>>>(ph, pl, vh, vl, oth, otl);
        gemm_bb<2><<<dim3(4, 8, 4), 256, SMG>>>(wh + OFF_O + lw, wl + OFF_O + lw, oth, otl,
                                                e, e, nullptr, nullptr, 512, 512, 0);
        frame_norm_k<<<lnG, lnB>>>(e, n2_w + (size_t)i * 1024, n2_b + (size_t)i * 1024, h);
        tsplit<<<tsG512, 256>>>(h, hth, htl, 512);
        long lf = (long)i * 2097152;
        gemm_bb<3><<<dim3(4, 32, 4), 256, SMG>>>(wh + OFF_F1 + lf, wl + OFF_F1 + lf, hth, htl,
                                                 nullptr, nullptr, ath, atl, 2048, 512, 0);
        gemm_bb<2><<<dim3(4, 8, 4), 256, SMG>>>(wh + OFF_F2 + lf, wl + OFF_F2 + lf, ath, atl,
                                                e, e, nullptr, nullptr, 512, 2048, 0);
    }

    // decoder
    tsplit<<<tsG512, 256>>>(e, hth, htl, 512);
    gemm_bb<0><<<dim3(4, 16, 4), 256, SMG>>>(wh + OFF_D1, wl + OFF_D1, hth, htl, nullptr, big, nullptr, nullptr, 1024, 512, 0);
    mix_k<true, false><<<8192, 256>>>(big, d1_dw, nullptr, s, 1024);
    tsplit<<<tsG1024, 256>>>(s, ath, atl, 1024);
    gemm_bb<0><<<dim3(4, 16, 4), 256, SMG>>>(wh + OFF_D2, wl + OFF_D2, ath, atl, nullptr, big + 2097152, nullptr, nullptr, 1024, 1024, 0);
    mix_k<false, false><<<8192, 256>>>(big + 2097152, d2_dw, nullptr, s + 4194304, 1024);
    gemm_bb<0><<<dim3(4, 16, 4), 256, SMG>>>(wh + OFF_DI, wl + OFF_DI, hth, htl, nullptr, big, nullptr, nullptr, 1024, 512, 0);
    mix_k<false, true><<<8192, 256>>>(big, di_dw, s + 4194304, out, 1024);
}